// round 9
// baseline (speedup 1.0000x reference)
#include <cuda_runtime.h>

// out = kipf - lbda[row] * input
// input, kipf: [100000, 256] fp32; lbda: [100000] fp32
// R1 codegen (1 float4/thread, 22 regs) with 128-thread blocks: same resident
// warp count per SM (16 CTAs x 4 warps), but 2x finer block scheduling
// granularity for last-wave balance. Final search point; R1 is fallback.

__global__ __launch_bounds__(128) void damping_kernel(
    const float4* __restrict__ input4,
    const float4* __restrict__ kipf4,
    const float*  __restrict__ lbda,
    float4* __restrict__ out4,
    int n4)  // total float4 count
{
    int i = blockIdx.x * blockDim.x + threadIdx.x;
    if (i >= n4) return;

    int row = i >> 6;               // 64 float4 per 256-float row
    float l = __ldg(&lbda[row]);    // broadcast across 64 consecutive threads

    float4 a = input4[i];
    float4 k = kipf4[i];

    float4 r;
    r.x = fmaf(-l, a.x, k.x);
    r.y = fmaf(-l, a.y, k.y);
    r.z = fmaf(-l, a.z, k.z);
    r.w = fmaf(-l, a.w, k.w);

    out4[i] = r;
}

extern "C" void kernel_launch(void* const* d_in, const int* in_sizes, int n_in,
                              void* d_out, int out_size) {
    const float4* input4 = (const float4*)d_in[0];   // input_term
    const float4* kipf4  = (const float4*)d_in[1];   // kipf_term
    const float*  lbda   = (const float*)d_in[2];    // lbda
    // d_in[3] = spar (unused scalar, always 1)

    int n  = out_size;        // 25,600,000
    int n4 = n / 4;           // 6,400,000

    int threads = 128;
    int blocks  = (n4 + threads - 1) / threads;  // 50000
    damping_kernel<<<blocks, threads>>>(input4, kipf4, lbda, (float4*)d_out, n4);
}